// round 2
// baseline (speedup 1.0000x reference)
#include <cuda_runtime.h>
#include <cuda_bf16.h>
#include <cstddef>

// Problem constants (fixed by the reference):
//   B=64, NTH=56, NTW=56  -> T = 200704 tiles (divisible by 128)
//   M = 8 slots/tile, DF = 8 flux fields, D = 2 + DF + 1 = 11 output fields
static constexpr float FAR_SENTINEL = 100.0f;
static constexpr float FLT_BIG = 3.402823466e38f;
static constexpr int   TPB = 128;   // threads per block == tiles per block

__global__ __launch_bounds__(TPB) void match_scatter_kernel(
    const float* __restrict__ est_locs,    // [T, 8, 2]
    const float* __restrict__ true_locs,   // [T, 8, 2]
    const float* __restrict__ true_fluxes, // [T, 8, 8]
    const int*   __restrict__ est_ns,      // [T]
    const int*   __restrict__ true_ns,     // [T]
    float*       __restrict__ out,         // [T, 8, 11]
    int T)
{
    __shared__ unsigned int mpack[TPB];   // per tile: 8 nibbles, slot p -> src row (8 = none)

    const int tid = threadIdx.x;
    const int t   = blockIdx.x * TPB + tid;

    // ================= Phase A: per-thread matching =================
    unsigned int pack = 0x88888888u;      // all slots unmatched
    if (t < T) {
        const int n_e = est_ns[t];
        const int n_t = true_ns[t];

        // true locs: 4x float4, masked to FAR once
        float tlx[8], tly[8];
        {
            const float4* tp = reinterpret_cast<const float4*>(true_locs) + (size_t)t * 4;
            #pragma unroll
            for (int i = 0; i < 4; ++i) {
                float4 v = tp[i];
                tlx[2*i]   = v.x; tly[2*i]   = v.y;
                tlx[2*i+1] = v.z; tly[2*i+1] = v.w;
            }
            #pragma unroll
            for (int s = 0; s < 8; ++s) {
                const bool on = s < n_t;
                tlx[s] = on ? tlx[s] : FAR_SENTINEL;
                tly[s] = on ? tly[s] : FAR_SENTINEL;
            }
        }

        float colmin[8];
        int   colarg[8];   // match1[s] = best est row for true col s
        int   match2[8];   // best true col for est row i
        #pragma unroll
        for (int s = 0; s < 8; ++s) { colmin[s] = FLT_BIG; colarg[s] = 0; }

        // stream est locs: one float4 = two est points, consumed immediately
        const float4* ep = reinterpret_cast<const float4*>(est_locs) + (size_t)t * 4;
        #pragma unroll
        for (int iv = 0; iv < 4; ++iv) {
            const float4 e = ep[iv];
            #pragma unroll
            for (int h = 0; h < 2; ++h) {
                const int i = 2*iv + h;
                const bool e_on = i < n_e;
                const float ex = e_on ? (h ? e.z : e.x) : FAR_SENTINEL;
                const float ey = e_on ? (h ? e.w : e.y) : FAR_SENTINEL;
                float rmin = FLT_BIG;
                int   rarg = 0;
                #pragma unroll
                for (int s = 0; s < 8; ++s) {
                    const float dx = __fadd_rn(ex, -tlx[s]);
                    const float dy = __fadd_rn(ey, -tly[s]);
                    // unfused mul/add + sqrt: bit-matches the reference (tie safety)
                    const float d  = sqrtf(__fadd_rn(__fmul_rn(dx, dx), __fmul_rn(dy, dy)));
                    if (d < rmin)      { rmin = d;      rarg = s; }
                    if (d < colmin[s]) { colmin[s] = d; colarg[s] = i; }
                }
                match2[i] = rarg;
            }
        }

        // one-to-one condition (constant indexing only)
        bool ok[8];
        #pragma unroll
        for (int s = 0; s < 8; ++s) {
            const int m2 = match2[s];
            bool eq = false;
            #pragma unroll
            for (int j = 0; j < 8; ++j)
                eq |= (m2 == j) & (colarg[j] == s);
            ok[s] = eq && (colarg[s] < n_e) && (m2 < n_t);
        }

        // pack: slot p gets match2[s] of the LAST s with ok[s] && colarg[s]==p
        pack = 0u;
        #pragma unroll
        for (int p = 0; p < 8; ++p) {
            int sp = 8;
            #pragma unroll
            for (int s = 0; s < 8; ++s)
                if (ok[s] && (colarg[s] == p)) sp = match2[s];
            pack |= (unsigned int)sp << (4 * p);
        }
    }
    mpack[tid] = pack;
    __syncthreads();

    // ================= Phase B: cooperative coalesced output =================
    // Block covers ntiles * 88 consecutive floats; consecutive threads write
    // consecutive floats (perfect coalescing). Gather reads are short
    // contiguous runs (locs: L1-hot lines; fluxes: 32B-aligned rows).
    const int    block_t0 = blockIdx.x * TPB;
    const int    ntiles   = min(TPB, T - block_t0);
    const int    total    = ntiles * 88;
    const size_t obase    = (size_t)block_t0 * 88;

    for (int idx = tid; idx < total; idx += TPB) {
        const unsigned int u   = (unsigned int)idx;
        const unsigned int tl  = u / 88u;            // tile local
        const unsigned int rem = u - tl * 88u;
        const unsigned int p   = rem / 11u;          // output slot
        const unsigned int f   = rem - p * 11u;      // field index 0..10
        const unsigned int sp  = (mpack[tl] >> (4u * p)) & 0xFu;

        float val = 0.0f;
        if (sp < 8u) {
            const size_t tg = (size_t)block_t0 + tl;
            if (f < 2u)
                val = true_locs[tg * 16 + sp * 2 + f];
            else if (f < 10u)
                val = true_fluxes[tg * 64 + sp * 8 + (f - 2u)];
            else
                val = 1.0f;    // matched implies sp < n_t -> indicator is 1
        }
        out[obase + idx] = val;
    }
}

extern "C" void kernel_launch(void* const* d_in, const int* in_sizes, int n_in,
                              void* d_out, int out_size)
{
    const float* est_locs    = (const float*)d_in[0];
    const float* true_locs   = (const float*)d_in[1];
    const float* true_fluxes = (const float*)d_in[2];
    const int*   est_ns      = (const int*)d_in[3];
    const int*   true_ns     = (const int*)d_in[4];
    float*       out         = (float*)d_out;

    const int T = in_sizes[3];   // number of tiles

    const int blocks = (T + TPB - 1) / TPB;
    match_scatter_kernel<<<blocks, TPB>>>(est_locs, true_locs, true_fluxes,
                                          est_ns, true_ns, out, T);
}

// round 3
// speedup vs baseline: 2.5133x; 2.5133x over previous
#include <cuda_runtime.h>
#include <cuda_bf16.h>
#include <cstddef>

// Problem constants (fixed by the reference):
//   B=64, NTH=56, NTW=56  -> T = 200704 tiles (divisible by 128)
//   M = 8 slots/tile, DF = 8 flux fields, D = 2 + DF + 1 = 11 output fields
static constexpr float FAR_SENTINEL = 100.0f;
static constexpr float FLT_BIG = 3.402823466e38f;
static constexpr int   TPB  = 128;   // threads per block == tiles per block
static constexpr int   SROW = 89;    // padded smem row stride (odd -> conflict-free)

__global__ __launch_bounds__(TPB) void match_scatter_kernel(
    const float* __restrict__ est_locs,    // [T, 8, 2]
    const float* __restrict__ true_locs,   // [T, 8, 2]
    const float* __restrict__ true_fluxes, // [T, 8, 8]
    const int*   __restrict__ est_ns,      // [T]
    const int*   __restrict__ true_ns,     // [T]
    float*       __restrict__ out,         // [T, 8, 11]
    int T)
{
    __shared__ float stile[TPB * SROW];    // per-tile 88-float output rows (padded)

    const int tid = threadIdx.x;
    const int t   = blockIdx.x * TPB + tid;

    // ================= Phase A: per-thread matching + smem staging =================
    if (t < T) {
        const int n_e = est_ns[t];
        const int n_t = true_ns[t];

        // raw true locs (kept unmasked for the gather)
        float tlx[8], tly[8];
        {
            const float4* tp = reinterpret_cast<const float4*>(true_locs) + (size_t)t * 4;
            #pragma unroll
            for (int i = 0; i < 4; ++i) {
                float4 v = tp[i];
                tlx[2*i]   = v.x; tly[2*i]   = v.y;
                tlx[2*i+1] = v.z; tly[2*i+1] = v.w;
            }
        }

        float colmin[8];
        int   colarg[8];   // match1[s] = best est row for true col s
        int   match2[8];   // best true col for est row i
        #pragma unroll
        for (int s = 0; s < 8; ++s) { colmin[s] = FLT_BIG; colarg[s] = 0; }

        // stream est locs: one float4 = two est points, consumed immediately
        const float4* ep = reinterpret_cast<const float4*>(est_locs) + (size_t)t * 4;
        #pragma unroll
        for (int iv = 0; iv < 4; ++iv) {
            const float4 e = ep[iv];
            #pragma unroll
            for (int h = 0; h < 2; ++h) {
                const int i = 2*iv + h;
                const bool e_on = i < n_e;
                const float ex = e_on ? (h ? e.z : e.x) : FAR_SENTINEL;
                const float ey = e_on ? (h ? e.w : e.y) : FAR_SENTINEL;
                float rmin = FLT_BIG;
                int   rarg = 0;
                #pragma unroll
                for (int s = 0; s < 8; ++s) {
                    const float tx = (s < n_t) ? tlx[s] : FAR_SENTINEL;
                    const float ty = (s < n_t) ? tly[s] : FAR_SENTINEL;
                    const float dx = __fadd_rn(ex, -tx);
                    const float dy = __fadd_rn(ey, -ty);
                    // unfused mul/add + sqrt: bit-matches the reference (tie safety)
                    const float d  = sqrtf(__fadd_rn(__fmul_rn(dx, dx), __fmul_rn(dy, dy)));
                    if (d < rmin)      { rmin = d;      rarg = s; }
                    if (d < colmin[s]) { colmin[s] = d; colarg[s] = i; }
                }
                match2[i] = rarg;
            }
        }

        // one-to-one condition (constant indexing only)
        bool ok[8];
        #pragma unroll
        for (int s = 0; s < 8; ++s) {
            const int m2 = match2[s];
            bool eq = false;
            #pragma unroll
            for (int j = 0; j < 8; ++j)
                eq |= (m2 == j) & (colarg[j] == s);
            ok[s] = eq && (colarg[s] < n_e) && (m2 < n_t);
        }

        // gather matched rows into this tile's smem output row
        const float4* fp   = reinterpret_cast<const float4*>(true_fluxes) + (size_t)t * 16;
        float*        srow = &stile[tid * SROW];

        #pragma unroll
        for (int p = 0; p < 8; ++p) {
            // scatter: last s with ok[s] && match1[s]==p wins (matches seq scatter)
            int sp = -1;
            #pragma unroll
            for (int s = 0; s < 8; ++s)
                if (ok[s] && (colarg[s] == p)) sp = match2[s];

            float* dst = srow + p * 11;
            if (sp >= 0) {
                // select raw loc from registers with constant indexing
                float lx = 0.f, ly = 0.f;
                #pragma unroll
                for (int j = 0; j < 8; ++j)
                    if (sp == j) { lx = tlx[j]; ly = tly[j]; }
                dst[0] = lx;
                dst[1] = ly;
                const float4 f0 = fp[sp*2 + 0];   // 32B flux row: sector-exact
                const float4 f1 = fp[sp*2 + 1];
                dst[2] = f0.x; dst[3] = f0.y; dst[4] = f0.z; dst[5] = f0.w;
                dst[6] = f1.x; dst[7] = f1.y; dst[8] = f1.z; dst[9] = f1.w;
                dst[10] = 1.0f;   // matched implies sp < n_t -> indicator is 1
            } else {
                #pragma unroll
                for (int f = 0; f < 11; ++f) dst[f] = 0.0f;
            }
        }
    }
    __syncthreads();

    // ================= Phase B: coalesced smem -> gmem copy =================
    const int block_t0 = blockIdx.x * TPB;
    const int ntiles   = min(TPB, T - block_t0);
    const int nvec     = ntiles * 22;                      // float4s this block owns
    float4*   op       = reinterpret_cast<float4*>(out) + (size_t)block_t0 * 22;

    for (int v = tid; v < nvec; v += TPB) {
        const int tl = v / 22;          // magic-multiply, cheap
        const int q  = v - tl * 22;
        const float* row = &stile[tl * SROW + q * 4];
        op[v] = make_float4(row[0], row[1], row[2], row[3]);
    }
}

extern "C" void kernel_launch(void* const* d_in, const int* in_sizes, int n_in,
                              void* d_out, int out_size)
{
    const float* est_locs    = (const float*)d_in[0];
    const float* true_locs   = (const float*)d_in[1];
    const float* true_fluxes = (const float*)d_in[2];
    const int*   est_ns      = (const int*)d_in[3];
    const int*   true_ns     = (const int*)d_in[4];
    float*       out         = (float*)d_out;

    const int T = in_sizes[3];   // number of tiles

    const int blocks = (T + TPB - 1) / TPB;
    match_scatter_kernel<<<blocks, TPB>>>(est_locs, true_locs, true_fluxes,
                                          est_ns, true_ns, out, T);
}

// round 6
// speedup vs baseline: 3.1454x; 1.2515x over previous
#include <cuda_runtime.h>
#include <cuda_bf16.h>
#include <cstddef>

// Problem constants (fixed by the reference):
//   B=64, NTH=56, NTW=56  -> T = 200704 tiles (= 784 * 256)
//   M = 8 slots/tile, DF = 8 flux fields, D = 2 + DF + 1 = 11 output fields
static constexpr float FAR_SENTINEL = 100.0f;
static constexpr float FLT_BIG = 3.402823466e38f;

__global__ __launch_bounds__(256, 4) void match_scatter_kernel(
    const float* __restrict__ est_locs,    // [T, 8, 2]
    const float* __restrict__ true_locs,   // [T, 8, 2]
    const float* __restrict__ true_fluxes, // [T, 8, 8]
    const int*   __restrict__ est_ns,      // [T]
    const int*   __restrict__ true_ns,     // [T]
    float*       __restrict__ out,         // [T, 8, 11]
    int T)
{
    const int t = blockIdx.x * blockDim.x + threadIdx.x;
    if (t >= T) return;

    const int n_e = est_ns[t];
    const int n_t = true_ns[t];

    // ---- true locs: 4x float4 load, mask to FAR once (hoisted out of 8x8) ----
    float tlx[8], tly[8];
    {
        const float4* tp = reinterpret_cast<const float4*>(true_locs) + (size_t)t * 4;
        #pragma unroll
        for (int i = 0; i < 4; ++i) {
            float4 v = tp[i];
            tlx[2*i]   = v.x; tly[2*i]   = v.y;
            tlx[2*i+1] = v.z; tly[2*i+1] = v.w;
        }
        #pragma unroll
        for (int s = 0; s < 8; ++s) {
            const bool on = s < n_t;
            tlx[s] = on ? tlx[s] : FAR_SENTINEL;
            tly[s] = on ? tly[s] : FAR_SENTINEL;
        }
    }

    // ---- 8x8 distance pass with IEEE sqrt (tie-merge must match reference) ----
    float colmin[8];
    int   colarg[8];                 // match1[s] = best est row for true col s
    unsigned int m2pack = 0u;        // match2[i] nibbles (best true col per est row)
    #pragma unroll
    for (int s = 0; s < 8; ++s) { colmin[s] = FLT_BIG; colarg[s] = 0; }

    const float4* ep = reinterpret_cast<const float4*>(est_locs) + (size_t)t * 4;
    #pragma unroll
    for (int iv = 0; iv < 4; ++iv) {
        const float4 e = ep[iv];
        #pragma unroll
        for (int h = 0; h < 2; ++h) {
            const int  i    = 2*iv + h;
            const bool e_on = i < n_e;
            const float ex = e_on ? (h ? e.z : e.x) : FAR_SENTINEL;
            const float ey = e_on ? (h ? e.w : e.y) : FAR_SENTINEL;
            float rmin = FLT_BIG;
            int   rarg = 0;
            #pragma unroll
            for (int s = 0; s < 8; ++s) {
                const float dx = __fadd_rn(ex, -tlx[s]);
                const float dy = __fadd_rn(ey, -tly[s]);
                // unfused + correctly-rounded sqrt: bit-matches reference ordering
                const float d  = __fsqrt_rn(__fadd_rn(__fmul_rn(dx, dx), __fmul_rn(dy, dy)));
                if (d < rmin)      { rmin = d;      rarg = s; }       // strict < keeps first
                if (d < colmin[s]) { colmin[s] = d; colarg[s] = i; }
            }
            m2pack |= (unsigned int)rarg << (4 * i);
        }
    }

    // pack match1 nibbles
    unsigned int m1pack = 0u;
    #pragma unroll
    for (int j = 0; j < 8; ++j)
        m1pack |= (unsigned int)colarg[j] << (4 * j);

    // ---- one-to-one + scatter pack (slot p -> source row, 8 = unmatched) ----
    // ok[s]: match1[match2[s]]==s && match1[s] < n_e && match2[s] < n_t
    // scatter: ascending s, last winner overwrites (matches sequential scatter)
    unsigned int spack = 0x88888888u;
    #pragma unroll
    for (int s = 0; s < 8; ++s) {
        const int m2   = (int)((m2pack >> (4 * s)) & 0xFu);
        const int m1c2 = (int)((m1pack >> (4 * m2)) & 0xFu);   // dynamic shift
        const bool ok  = (m1c2 == s) && (colarg[s] < n_e) && (m2 < n_t);
        if (ok) {
            const int sh = colarg[s] * 4;
            spack = (spack & ~(0xFu << sh)) | ((unsigned int)m2 << sh);
        }
    }

    // ---- output: two halves of 4 slots (44 floats = 11 float4 each) ----
    const float4* fp      = reinterpret_cast<const float4*>(true_fluxes) + (size_t)t * 16;
    const float*  tl_base = true_locs + (size_t)t * 16;       // raw locs, L1-hot
    float4*       op      = reinterpret_cast<float4*>(out) + (size_t)t * 22;

    #pragma unroll
    for (int half = 0; half < 2; ++half) {
        float buf[44];
        #pragma unroll
        for (int k = 0; k < 44; ++k) buf[k] = 0.0f;

        #pragma unroll
        for (int pl = 0; pl < 4; ++pl) {
            const int p  = half * 4 + pl;
            const int sp = (int)((spack >> (4 * p)) & 0xFu);
            if (sp < 8) {
                float* dst = buf + pl * 11;
                dst[0] = tl_base[sp*2 + 0];
                dst[1] = tl_base[sp*2 + 1];
                const float4 f0 = fp[sp*2 + 0];   // 32B-aligned flux row
                const float4 f1 = fp[sp*2 + 1];
                dst[2] = f0.x; dst[3] = f0.y; dst[4] = f0.z; dst[5] = f0.w;
                dst[6] = f1.x; dst[7] = f1.y; dst[8] = f1.z; dst[9] = f1.w;
                dst[10] = 1.0f;                   // matched implies sp < n_t
            }
        }

        #pragma unroll
        for (int q = 0; q < 11; ++q)
            op[half * 11 + q] = make_float4(buf[4*q + 0], buf[4*q + 1],
                                            buf[4*q + 2], buf[4*q + 3]);
    }
}

extern "C" void kernel_launch(void* const* d_in, const int* in_sizes, int n_in,
                              void* d_out, int out_size)
{
    const float* est_locs    = (const float*)d_in[0];
    const float* true_locs   = (const float*)d_in[1];
    const float* true_fluxes = (const float*)d_in[2];
    const int*   est_ns      = (const int*)d_in[3];
    const int*   true_ns     = (const int*)d_in[4];
    float*       out         = (float*)d_out;

    const int T = in_sizes[3];   // number of tiles

    const int threads = 256;
    const int blocks  = (T + threads - 1) / threads;
    match_scatter_kernel<<<blocks, threads>>>(est_locs, true_locs, true_fluxes,
                                              est_ns, true_ns, out, T);
}

// round 7
// speedup vs baseline: 3.8406x; 1.2210x over previous
#include <cuda_runtime.h>
#include <cuda_bf16.h>
#include <cstddef>

// Problem constants (fixed by the reference):
//   B=64, NTH=56, NTW=56  -> T = 200704 tiles; 2 threads per tile.
//   M = 8 slots/tile, DF = 8 flux fields, D = 2 + DF + 1 = 11 output fields
static constexpr float FAR_SENTINEL = 100.0f;
static constexpr float FLT_BIG = 3.402823466e38f;

__global__ __launch_bounds__(256, 5) void match_scatter_kernel(
    const float* __restrict__ est_locs,    // [T, 8, 2]
    const float* __restrict__ true_locs,   // [T, 8, 2]
    const float* __restrict__ true_fluxes, // [T, 8, 8]
    const int*   __restrict__ est_ns,      // [T]
    const int*   __restrict__ true_ns,     // [T]
    float*       __restrict__ out,         // [T, 8, 11]
    int T)
{
    const int g    = blockIdx.x * blockDim.x + threadIdx.x;
    const int t    = g >> 1;          // tile
    const int half = g & 1;           // 0: est rows 0-3, slots 0-3; 1: rows 4-7, slots 4-7
    const bool live = (t < T);
    const int tc   = live ? t : (T - 1);   // clamp for safe loads; shfls stay uniform

    const int n_e = est_ns[tc];
    const int n_t = true_ns[tc];

    // ---- true locs: all 8 points, mask to FAR once (pair-broadcast loads) ----
    float tlx[8], tly[8];
    {
        const float4* tp = reinterpret_cast<const float4*>(true_locs) + (size_t)tc * 4;
        #pragma unroll
        for (int i = 0; i < 4; ++i) {
            float4 v = tp[i];
            tlx[2*i]   = v.x; tly[2*i]   = v.y;
            tlx[2*i+1] = v.z; tly[2*i+1] = v.w;
        }
        #pragma unroll
        for (int s = 0; s < 8; ++s) {
            const bool on = s < n_t;
            tlx[s] = on ? tlx[s] : FAR_SENTINEL;
            tly[s] = on ? tly[s] : FAR_SENTINEL;
        }
    }

    // ---- this lane's 4 est rows: 8x4 distance sub-block, exact sqrt ----
    float colmin[8];
    int   colarg[8];                  // partial match1 over this lane's rows
    unsigned int m2own = 0u;          // match2 nibbles at GLOBAL row positions
    #pragma unroll
    for (int s = 0; s < 8; ++s) { colmin[s] = FLT_BIG; colarg[s] = 4*half; }

    {
        const float4* ep = reinterpret_cast<const float4*>(est_locs)
                         + (size_t)tc * 4 + 2*half;
        #pragma unroll
        for (int iv = 0; iv < 2; ++iv) {
            const float4 e = ep[iv];
            #pragma unroll
            for (int hh = 0; hh < 2; ++hh) {
                const int  il = 2*iv + hh;          // local row 0..3
                const int  ri = 4*half + il;        // global row
                const bool e_on = ri < n_e;
                const float ex = e_on ? (hh ? e.z : e.x) : FAR_SENTINEL;
                const float ey = e_on ? (hh ? e.w : e.y) : FAR_SENTINEL;
                float rmin = FLT_BIG;
                int   rarg = 0;
                #pragma unroll
                for (int s = 0; s < 8; ++s) {
                    const float dx = __fadd_rn(ex, -tlx[s]);
                    const float dy = __fadd_rn(ey, -tly[s]);
                    // unfused + correctly-rounded sqrt: bit-matches reference
                    const float d = __fsqrt_rn(__fadd_rn(__fmul_rn(dx, dx),
                                                         __fmul_rn(dy, dy)));
                    if (d < rmin)      { rmin = d;      rarg = s;  }  // first-index on tie
                    if (d < colmin[s]) { colmin[s] = d; colarg[s] = ri; }
                }
                m2own |= (unsigned int)rarg << (4 * ri);
            }
        }
    }

    // ---- merge column argmins across the pair (lower global row wins ties) ----
    // Even lane owns rows 0-3 (lower), so on equal distance the EVEN value wins.
    const bool i_am_odd = (half != 0);
    #pragma unroll
    for (int s = 0; s < 8; ++s) {
        const float ov = __shfl_xor_sync(0xffffffffu, colmin[s], 1);
        const int   oa = __shfl_xor_sync(0xffffffffu, colarg[s], 1);
        const bool take = (ov < colmin[s]) | ((ov == colmin[s]) & i_am_odd);
        colmin[s] = take ? ov : colmin[s];
        colarg[s] = take ? oa : colarg[s];
    }

    // full match2 nibble word (partner's nibbles are 0 where mine are set)
    const unsigned int m2full = m2own | __shfl_xor_sync(0xffffffffu, m2own, 1);

    // pack full match1 nibbles (merged colarg)
    unsigned int m1pack = 0u;
    #pragma unroll
    for (int j = 0; j < 8; ++j)
        m1pack |= (unsigned int)colarg[j] << (4 * j);

    // ---- one-to-one + scatter for THIS lane's 4 s values (ascending s) ----
    unsigned int spack = 0x88888888u;
    #pragma unroll
    for (int sl = 0; sl < 4; ++sl) {
        const int s    = 4*half + sl;
        const int m2   = (int)((m2full >> (4 * s)) & 0xFu);
        const int m1c2 = (int)((m1pack >> (4 * m2)) & 0xFu);
        const bool ok  = (m1c2 == s) && (colarg[s] < n_e) && (m2 < n_t);
        if (ok) {
            const int sh = colarg[s] * 4;
            spack = (spack & ~(0xFu << sh)) | ((unsigned int)m2 << sh);
        }
    }
    // merge pair spacks: odd lane's entries (s=4-7, later writes) take priority
    {
        const unsigned int other = __shfl_xor_sync(0xffffffffu, spack, 1);
        const unsigned int sp_odd  = i_am_odd ? spack : other;
        const unsigned int sp_even = i_am_odd ? other : spack;
        unsigned int merged = 0u;
        #pragma unroll
        for (int p = 0; p < 8; ++p) {
            const unsigned int no = (sp_odd  >> (4*p)) & 0xFu;
            const unsigned int ne = (sp_even >> (4*p)) & 0xFu;
            merged |= ((no != 8u) ? no : ne) << (4*p);
        }
        spack = merged;
    }

    if (!live) return;

    // ---- output: this lane writes slots 4h..4h+3 = 44 floats = 11 float4 ----
    const float4* fp      = reinterpret_cast<const float4*>(true_fluxes) + (size_t)t * 16;
    const float*  tl_base = true_locs + (size_t)t * 16;   // raw locs, L1-hot

    float buf[44];
    #pragma unroll
    for (int k = 0; k < 44; ++k) buf[k] = 0.0f;

    #pragma unroll
    for (int pl = 0; pl < 4; ++pl) {
        const int p  = 4*half + pl;
        const int sp = (int)((spack >> (4 * p)) & 0xFu);
        if (sp < 8) {
            float* dst = buf + pl * 11;
            dst[0] = tl_base[sp*2 + 0];
            dst[1] = tl_base[sp*2 + 1];
            const float4 f0 = fp[sp*2 + 0];   // 32B-aligned flux row
            const float4 f1 = fp[sp*2 + 1];
            dst[2] = f0.x; dst[3] = f0.y; dst[4] = f0.z; dst[5] = f0.w;
            dst[6] = f1.x; dst[7] = f1.y; dst[8] = f1.z; dst[9] = f1.w;
            dst[10] = 1.0f;                   // matched implies sp < n_t
        }
    }

    float4* op = reinterpret_cast<float4*>(out) + (size_t)t * 22 + half * 11;
    #pragma unroll
    for (int q = 0; q < 11; ++q)
        op[q] = make_float4(buf[4*q + 0], buf[4*q + 1],
                            buf[4*q + 2], buf[4*q + 3]);
}

extern "C" void kernel_launch(void* const* d_in, const int* in_sizes, int n_in,
                              void* d_out, int out_size)
{
    const float* est_locs    = (const float*)d_in[0];
    const float* true_locs   = (const float*)d_in[1];
    const float* true_fluxes = (const float*)d_in[2];
    const int*   est_ns      = (const int*)d_in[3];
    const int*   true_ns     = (const int*)d_in[4];
    float*       out         = (float*)d_out;

    const int T = in_sizes[3];   // number of tiles

    const int threads = 256;
    const int total   = 2 * T;   // two threads per tile
    const int blocks  = (total + threads - 1) / threads;
    match_scatter_kernel<<<blocks, threads>>>(est_locs, true_locs, true_fluxes,
                                              est_ns, true_ns, out, T);
}

// round 8
// speedup vs baseline: 4.0808x; 1.0626x over previous
#include <cuda_runtime.h>
#include <cuda_bf16.h>
#include <cstddef>

// Problem constants (fixed by the reference):
//   B=64, NTH=56, NTW=56  -> T = 200704 tiles; 4 threads (a "quad") per tile.
//   M = 8 slots/tile, DF = 8 flux fields, D = 2 + DF + 1 = 11 output fields
static constexpr float FAR_SENTINEL = 100.0f;
static constexpr float FLT_BIG = 3.402823466e38f;

__device__ __forceinline__ unsigned int nib(unsigned int w, int i) {
    return (w >> (4 * i)) & 0xFu;
}

__global__ __launch_bounds__(256, 5) void match_scatter_kernel(
    const float* __restrict__ est_locs,    // [T, 8, 2]
    const float* __restrict__ true_locs,   // [T, 8, 2]
    const float* __restrict__ true_fluxes, // [T, 8, 8]
    const int*   __restrict__ est_ns,      // [T]
    const int*   __restrict__ true_ns,     // [T]
    float*       __restrict__ out,         // [T, 8, 11]
    int T)
{
    const int g   = blockIdx.x * blockDim.x + threadIdx.x;
    const int t   = g >> 2;               // tile
    const int l   = g & 3;                // quad lane: est rows 2l,2l+1; s = 2l,2l+1
    const bool live = (t < T);
    const int tc  = live ? t : (T - 1);   // clamp for safe loads; shfls stay uniform

    const int n_e = est_ns[tc];
    const int n_t = true_ns[tc];

    // ---- true locs: all 8 points, masked to FAR once (quad-broadcast loads) ----
    float tlx[8], tly[8];
    {
        const float4* tp = reinterpret_cast<const float4*>(true_locs) + (size_t)tc * 4;
        #pragma unroll
        for (int i = 0; i < 4; ++i) {
            float4 v = tp[i];
            tlx[2*i]   = v.x; tly[2*i]   = v.y;
            tlx[2*i+1] = v.z; tly[2*i+1] = v.w;
        }
        #pragma unroll
        for (int s = 0; s < 8; ++s) {
            const bool on = s < n_t;
            tlx[s] = on ? tlx[s] : FAR_SENTINEL;
            tly[s] = on ? tly[s] : FAR_SENTINEL;
        }
    }

    // ---- this lane's 2 est rows: 8x2 distance sub-block, exact sqrt ----
    float colmin[8];
    int   colarg[8];                  // partial match1 over this lane's rows
    unsigned int m2own = 0u;          // match2 nibbles at GLOBAL row positions
    #pragma unroll
    for (int s = 0; s < 8; ++s) { colmin[s] = FLT_BIG; colarg[s] = 2*l; }

    {
        // one float4 = this lane's two est points; consecutive lanes -> consecutive 16B
        const float4 e = reinterpret_cast<const float4*>(est_locs)[(size_t)tc * 4 + l];
        #pragma unroll
        for (int hh = 0; hh < 2; ++hh) {
            const int  ri   = 2*l + hh;           // global est row
            const bool e_on = ri < n_e;
            const float ex = e_on ? (hh ? e.z : e.x) : FAR_SENTINEL;
            const float ey = e_on ? (hh ? e.w : e.y) : FAR_SENTINEL;
            float rmin = FLT_BIG;
            int   rarg = 0;
            #pragma unroll
            for (int s = 0; s < 8; ++s) {
                const float dx = __fadd_rn(ex, -tlx[s]);
                const float dy = __fadd_rn(ey, -tly[s]);
                // unfused + correctly-rounded sqrt: bit-matches reference ordering
                const float d = __fsqrt_rn(__fadd_rn(__fmul_rn(dx, dx),
                                                     __fmul_rn(dy, dy)));
                if (d < rmin)      { rmin = d;      rarg = s;  }   // first-index on tie
                if (d < colmin[s]) { colmin[s] = d; colarg[s] = ri; }
            }
            m2own |= (unsigned int)rarg << (4 * ri);
        }
    }

    // ---- merge column argmins across the quad (lower global row wins ties).
    //      Each round merges disjoint ORDERED row ranges, so "lower group wins
    //      on equal distance" == reference first-occurrence argmin. ----
    #pragma unroll
    for (int m = 1; m <= 2; m <<= 1) {
        const bool partner_lower = (l & m) != 0;
        #pragma unroll
        for (int s = 0; s < 8; ++s) {
            const float ov = __shfl_xor_sync(0xffffffffu, colmin[s], m);
            const int   oa = __shfl_xor_sync(0xffffffffu, colarg[s], m);
            const bool take = (ov < colmin[s]) | ((ov == colmin[s]) & partner_lower);
            colmin[s] = take ? ov : colmin[s];
            colarg[s] = take ? oa : colarg[s];
        }
    }

    // full match2 nibble word (disjoint nibbles -> OR-reduce)
    unsigned int m2full = m2own;
    m2full |= __shfl_xor_sync(0xffffffffu, m2full, 1);
    m2full |= __shfl_xor_sync(0xffffffffu, m2full, 2);

    // pack full match1 nibbles (merged colarg, identical on all quad lanes)
    unsigned int m1pack = 0u;
    #pragma unroll
    for (int j = 0; j < 8; ++j)
        m1pack |= (unsigned int)colarg[j] << (4 * j);

    // ---- one-to-one + scatter for THIS lane's 2 s values (ascending s) ----
    // ok[s]: match1[match2[s]]==s && match1[s] < n_e && match2[s] < n_t
    unsigned int spack = 0x88888888u;
    #pragma unroll
    for (int sl = 0; sl < 2; ++sl) {
        const int s    = 2*l + sl;
        const int m2   = (int)((m2full >> (4 * s)) & 0xFu);
        const int m1c2 = (int)((m1pack >> (4 * m2)) & 0xFu);
        const int c1   = (int)((m1pack >> (4 * s)) & 0xFu);   // match1[s]
        const bool ok  = (m1c2 == s) && (c1 < n_e) && (m2 < n_t);
        if (ok) {
            const int sh = c1 * 4;
            spack = (spack & ~(0xFu << sh)) | ((unsigned int)m2 << sh);
        }
    }
    // merge quad spacks: higher-s lane (later reference write) takes priority.
    // nibble==8 <=> bit3 set (values are 0..8) -> cheap mask expansion.
    #pragma unroll
    for (int m = 1; m <= 2; m <<= 1) {
        const unsigned int other = __shfl_xor_sync(0xffffffffu, spack, m);
        const unsigned int hi = (l & m) ? spack : other;   // higher-s lane's word
        const unsigned int lo = (l & m) ? other : spack;
        const unsigned int msk = ((hi & 0x88888888u) >> 3) * 15u; // nibbles where hi==8
        spack = (hi & ~msk) | (lo & msk);
    }

    if (!live || l >= 2) return;   // lanes 0,1 write halves 0,1

    // ---- output: this lane writes slots 4l..4l+3 = 44 floats = 11 float4 ----
    const float4* fp      = reinterpret_cast<const float4*>(true_fluxes) + (size_t)t * 16;
    const float*  tl_base = true_locs + (size_t)t * 16;   // raw locs, L1-hot

    float buf[44];
    #pragma unroll
    for (int k = 0; k < 44; ++k) buf[k] = 0.0f;

    #pragma unroll
    for (int pl = 0; pl < 4; ++pl) {
        const int p  = 4*l + pl;
        const int sp = (int)nib(spack, p);
        if (sp < 8) {
            float* dst = buf + pl * 11;
            dst[0] = tl_base[sp*2 + 0];
            dst[1] = tl_base[sp*2 + 1];
            const float4 f0 = fp[sp*2 + 0];   // 32B-aligned flux row
            const float4 f1 = fp[sp*2 + 1];
            dst[2] = f0.x; dst[3] = f0.y; dst[4] = f0.z; dst[5] = f0.w;
            dst[6] = f1.x; dst[7] = f1.y; dst[8] = f1.z; dst[9] = f1.w;
            dst[10] = 1.0f;                   // matched implies sp < n_t
        }
    }

    float4* op = reinterpret_cast<float4*>(out) + (size_t)t * 22 + l * 11;
    #pragma unroll
    for (int q = 0; q < 11; ++q)
        op[q] = make_float4(buf[4*q + 0], buf[4*q + 1],
                            buf[4*q + 2], buf[4*q + 3]);
}

extern "C" void kernel_launch(void* const* d_in, const int* in_sizes, int n_in,
                              void* d_out, int out_size)
{
    const float* est_locs    = (const float*)d_in[0];
    const float* true_locs   = (const float*)d_in[1];
    const float* true_fluxes = (const float*)d_in[2];
    const int*   est_ns      = (const int*)d_in[3];
    const int*   true_ns     = (const int*)d_in[4];
    float*       out         = (float*)d_out;

    const int T = in_sizes[3];   // number of tiles

    const int threads = 256;
    const long long total = 4LL * T;      // four threads per tile
    const int blocks = (int)((total + threads - 1) / threads);
    match_scatter_kernel<<<blocks, threads>>>(est_locs, true_locs, true_fluxes,
                                              est_ns, true_ns, out, T);
}